// round 16
// baseline (speedup 1.0000x reference)
#include <cuda_runtime.h>
#include <cuda_fp16.h>
#include <cstddef>
#include <cstdint>

// ---------------------------------------------------------------------------
// Problem constants
// ---------------------------------------------------------------------------
#define BB 4
#define LL 2048
#define DD 1024
#define HH 16
#define DK 64
#define DV 64
#define DFF 4096
#define ROWS (BB * LL)          // 8192
#define Y_ELEMS ((size_t)ROWS * DD)
#define NROWS_ATT ((size_t)BB * HH * LL)       // 131072

// ---------------------------------------------------------------------------
// Scratch (device globals: allocation-free rule)
// ---------------------------------------------------------------------------
__device__ __half g_x16[ROWS * DD];
__device__ __half g_q16[ROWS * DD];
__device__ __half g_k16[ROWS * DD];
__device__ __half g_vt16[ROWS * DD];       // V^T: [H*DV, ROWS]
__device__ __half g_o16[ROWS * DD];
__device__ __half g_z16[ROWS * DD];
__device__ __half g_h16[(size_t)ROWS * DFF];
__device__ float  g_y[ROWS * DD];
__device__ __half g_e16[(size_t)BB * HH * LL * LL];   // unnormalized exp scores
__device__ float  g_sum[NROWS_ATT];                   // per-row sums (atomic)
__device__ float  g_inv[NROWS_ATT];                   // per-row 1/sum
// fp16 weights
__device__ __half g_wq16[DD * DD];
__device__ __half g_wk16[DD * DD];
__device__ __half g_wv16[DD * DD];
__device__ __half g_fc16[DD * DD];
__device__ __half g_w116[DFF * DD];
__device__ __half g_w216[DD * DFF];

// ---------------------------------------------------------------------------
// Helpers
// ---------------------------------------------------------------------------
__device__ __forceinline__ uint32_t smem_u32(const void* p) {
    uint32_t a;
    asm("{ .reg .u64 t; cvta.to.shared.u64 t, %1; cvt.u32.u64 %0, t; }" : "=r"(a) : "l"(p));
    return a;
}
__device__ __forceinline__ void cp16(uint32_t s, const void* g) {
    asm volatile("cp.async.cg.shared.global [%0], [%1], 16;" :: "r"(s), "l"(g));
}
#define CP_COMMIT() asm volatile("cp.async.commit_group;" ::: "memory")
#define SWZ(off) ((off) ^ (((off) >> 3) & 0x70))

#define LDSM4(r, addr) \
    asm volatile("ldmatrix.sync.aligned.m8n8.x4.shared.b16 {%0,%1,%2,%3}, [%4];" \
                 : "=r"((r)[0]), "=r"((r)[1]), "=r"((r)[2]), "=r"((r)[3]) : "r"(addr))

__device__ __forceinline__ void mma16(float* c, const uint32_t* a, uint32_t b0, uint32_t b1) {
    asm volatile(
        "mma.sync.aligned.m16n8k16.row.col.f32.f16.f16.f32 "
        "{%0,%1,%2,%3}, {%4,%5,%6,%7}, {%8,%9}, {%0,%1,%2,%3};"
        : "+f"(c[0]), "+f"(c[1]), "+f"(c[2]), "+f"(c[3])
        : "r"(a[0]), "r"(a[1]), "r"(a[2]), "r"(a[3]), "r"(b0), "r"(b1));
}

__device__ __forceinline__ float fast_exp(float x) {
    x = fmaxf(x, -87.0f);
    float t = x * 1.4426950408889634f;
    float fi = floorf(t);
    float y = fmaf(fi, -0.6931471805599453f, x);
    int i = (int)fi;
    float p = 1.9841270e-4f;
    p = fmaf(p, y, 1.3888889e-3f);
    p = fmaf(p, y, 8.3333333e-3f);
    p = fmaf(p, y, 4.1666667e-2f);
    p = fmaf(p, y, 1.6666666e-1f);
    p = fmaf(p, y, 0.5f);
    p = fmaf(p, y, 1.0f);
    p = fmaf(p, y, 1.0f);
    return __int_as_float((i + 127) << 23) * p;
}

// ---------------------------------------------------------------------------
// fp16 NT GEMM: C[M,N] = A[M,K] @ B[N,K]^T  (fp32 accum)
// BM=128, BK=64 halves, 3-stage cp.async, 256 threads, ldmatrix fragments.
// flags: 1=relu, 2=fp16 out, 4=exp epilogue (E fp16 + atomic row sums),
//        8=per-row scale, 16=stream A-tile * rowscale to attn_out (fp32).
// ---------------------------------------------------------------------------
template <int BN, int WM>
__global__ void __launch_bounds__(256, 2)
h_gemm(const __half* __restrict__ A, const __half* __restrict__ B, void* Cv,
       const float* __restrict__ bias, const float* __restrict__ resid,
       const float* __restrict__ prior, const int* __restrict__ maskp,
       const float* __restrict__ rowscale, float* __restrict__ sums,
       float* __restrict__ attn_out, int flags,
       int K, int lda, int ldb, int ldc,
       long long sAo, long long sAi, long long sBo, long long sBi,
       long long sCo, long long sCi, int zInner) {
    constexpr int WMT = 128 / WM;
    constexpr int MT = WMT / 16;
    constexpr int STAGEB = (128 + BN) * 128;
    extern __shared__ char smc[];
    uint32_t sbase = smem_u32(smc);

    int tid = threadIdx.x;
    int wid = tid >> 5, lane = tid & 31;
    int t4 = lane >> 2, tq = lane & 3;
    int wm = wid % WM, wn = wid / WM;
    int l16 = lane & 15, lh = (lane >> 4) << 3;

    int z = blockIdx.z;
    int zo = z / zInner, zi = z - zo * zInner;
    A += (size_t)zo * sAo + (size_t)zi * sAi;
    B += (size_t)zo * sBo + (size_t)zi * sBi;
    size_t coff = (size_t)zo * sCo + (size_t)zi * sCi;
    float* C32 = (float*)Cv + coff;
    __half* C16 = (__half*)Cv + coff;
    const float* Rp = resid ? resid + coff : nullptr;
    const float* priorp = (flags & 4) ? prior + (size_t)zo * LL * LL : nullptr;
    const int* maskb = (flags & 4) ? maskp + zo * LL : nullptr;
    const float* rsp = (flags & 8) ? rowscale + (size_t)z * LL : nullptr;
    float* sump = (flags & 4) ? sums + (size_t)z * LL : nullptr;
    float* attp = (flags & 16) ? attn_out + (size_t)z * LL * LL : nullptr;
    int bm = blockIdx.y * 128;
    int bn = blockIdx.x * BN;

    float acc[MT][4][4];
#pragma unroll
    for (int mi = 0; mi < MT; mi++)
#pragma unroll
        for (int t = 0; t < 4; t++)
#pragma unroll
            for (int j = 0; j < 4; j++) acc[mi][t][j] = 0.f;

    int nk = K >> 6;

    auto load_stage = [&](int c) {
        int s = c % 3;
        int k0 = c << 6;
        uint32_t ab = sbase + s * STAGEB;
        uint32_t bb = ab + 128 * 128;
#pragma unroll
        for (int it = 0; it < 4; it++) {
            int f = it * 256 + tid;
            int row = f >> 3, c8 = f & 7;
            uint32_t off = row * 128 + c8 * 16;
            cp16(ab + SWZ(off), A + (size_t)(bm + row) * lda + k0 + c8 * 8);
        }
#pragma unroll
        for (int it = 0; it < BN / 32; it++) {
            int f = it * 256 + tid;
            int row = f >> 3, c8 = f & 7;
            uint32_t off = row * 128 + c8 * 16;
            cp16(bb + SWZ(off), B + (size_t)(bn + row) * ldb + k0 + c8 * 8);
        }
        CP_COMMIT();
    };

    load_stage(0);
    if (nk > 1) load_stage(1);
    for (int c = 0; c < nk; c++) {
        if (c + 2 < nk) {
            load_stage(c + 2);
            asm volatile("cp.async.wait_group 2;" ::: "memory");
        } else {
            asm volatile("cp.async.wait_group 0;" ::: "memory");
        }
        __syncthreads();
        uint32_t as0 = sbase + (c % 3) * STAGEB;
        uint32_t bs0 = as0 + 128 * 128;

        // ---- optional: stream normalized A tile (E * inv) to attn fp32 ----
        if (flags & 16) {
            int k0 = c << 6;
            const __half* asp = (const __half*)(smc + (c % 3) * STAGEB);
#pragma unroll
            for (int it = 0; it < 4; it++) {
                int f = it * 256 + tid;
                int row = f >> 3, c8 = f & 7;
                uint32_t off = (uint32_t)(row * 128 + c8 * 16);
                uint4 raw = *(const uint4*)((const char*)asp + SWZ(off));
                __half2* h2 = (__half2*)&raw;
                float iv = rsp[bm + row];          // FIX: global row index
                float2 f0 = __half22float2(h2[0]);
                float2 f1 = __half22float2(h2[1]);
                float2 f2 = __half22float2(h2[2]);
                float2 f3 = __half22float2(h2[3]);
                float* op = attp + (size_t)(bm + row) * LL + k0 + c8 * 8;
                *(float4*)op = make_float4(f0.x * iv, f0.y * iv, f1.x * iv, f1.y * iv);
                *(float4*)(op + 4) = make_float4(f2.x * iv, f2.y * iv, f3.x * iv, f3.y * iv);
            }
        }

#pragma unroll
        for (int ks = 0; ks < 4; ks++) {
            int k0h = ks * 16;
            uint32_t a[MT][4];
#pragma unroll
            for (int mi = 0; mi < MT; mi++) {
                uint32_t off = (uint32_t)(wm * WMT + mi * 16 + l16) * 128 + (k0h + lh) * 2;
                LDSM4(a[mi], as0 + SWZ(off));
            }
            uint32_t b[2][4];
#pragma unroll
            for (int nj = 0; nj < 2; nj++) {
                uint32_t off = (uint32_t)(wn * 32 + nj * 16 + l16) * 128 + (k0h + lh) * 2;
                LDSM4(b[nj], bs0 + SWZ(off));
            }
#pragma unroll
            for (int mi = 0; mi < MT; mi++)
#pragma unroll
                for (int t = 0; t < 4; t++)
                    mma16(acc[mi][t], a[mi], b[t >> 1][t & 1], b[t >> 1][(t & 1) + 2]);
        }
        __syncthreads();
    }

    // ---- epilogue ----
#pragma unroll
    for (int mi = 0; mi < MT; mi++) {
#pragma unroll
        for (int hf = 0; hf < 2; hf++) {
            int row = bm + wm * WMT + mi * 16 + t4 + hf * 8;
            float rs = rsp ? rsp[row] : 0.f;
            float rsum = 0.f;
#pragma unroll
            for (int t = 0; t < 4; t++) {
                int col = bn + wn * 32 + (t >> 1) * 16 + (t & 1) * 8 + tq * 2;
                float v0 = acc[mi][t][hf * 2 + 0];
                float v1 = acc[mi][t][hf * 2 + 1];
                if (flags & 4) {
                    // prior * mask * 1/8 then exp(v - 8) -> fp16 E + row sums
                    float2 pw = *(const float2*)(priorp + (size_t)row * LL + col);
                    int mk0 = maskb[col], mk1 = maskb[col + 1];
                    float s0 = mk0 ? v0 * (pw.x * 0.125f) : -1e9f;
                    float s1 = mk1 ? v1 * (pw.y * 0.125f) : -1e9f;
                    __half2 h = __floats2half2_rn(fast_exp(s0 - 8.0f), fast_exp(s1 - 8.0f));
                    *(__half2*)(C16 + (size_t)row * ldc + col) = h;
                    float2 hv = __half22float2(h);
                    rsum += hv.x + hv.y;
                    continue;
                }
                if (bias) { v0 += bias[col]; v1 += bias[col + 1]; }
                if (Rp) {
                    float2 r = *(const float2*)(Rp + (size_t)row * ldc + col);
                    v0 += r.x; v1 += r.y;
                }
                if (flags & 8) { v0 *= rs; v1 *= rs; }
                if (flags & 1) { v0 = fmaxf(v0, 0.f); v1 = fmaxf(v1, 0.f); }
                if (flags & 2) {
                    *(__half2*)(C16 + (size_t)row * ldc + col) = __floats2half2_rn(v0, v1);
                } else {
                    *(float2*)(C32 + (size_t)row * ldc + col) = make_float2(v0, v1);
                }
            }
            if (flags & 4) {
                rsum += __shfl_xor_sync(0xffffffffu, rsum, 1);
                rsum += __shfl_xor_sync(0xffffffffu, rsum, 2);
                if (tq == 0) atomicAdd(&sump[row], rsum);
            }
        }
    }
}

// ---------------------------------------------------------------------------
// Zero sums / invert sums
// ---------------------------------------------------------------------------
__global__ void zero_sums(float* __restrict__ s) {
    int i = blockIdx.x * 256 + threadIdx.x;
    if (i < (int)NROWS_ATT) s[i] = 0.f;
}
__global__ void inv_sums(const float* __restrict__ s, float* __restrict__ inv) {
    int i = blockIdx.x * 256 + threadIdx.x;
    if (i < (int)NROWS_ATT) inv[i] = 1.0f / s[i];
}

// ---------------------------------------------------------------------------
// One-shot weight conversion fp32 -> fp16
// ---------------------------------------------------------------------------
__global__ void cvt_all(const float* s0, const float* s1, const float* s2,
                        const float* s3, const float* s4, const float* s5,
                        __half* d0, __half* d1, __half* d2,
                        __half* d3, __half* d4, __half* d5) {
    int m = blockIdx.y;
    const float* s; __half* d; int n;
    switch (m) {
        case 0: s = s0; d = d0; n = DD * DD; break;
        case 1: s = s1; d = d1; n = DD * DD; break;
        case 2: s = s2; d = d2; n = DD * DD; break;
        case 3: s = s3; d = d3; n = DD * DD; break;
        case 4: s = s4; d = d4; n = DFF * DD; break;
        default: s = s5; d = d5; n = DFF * DD; break;
    }
    int i8 = (blockIdx.x * 256 + threadIdx.x) * 8;
    if (i8 < n) {
        float4 u = *(const float4*)(s + i8);
        float4 v = *(const float4*)(s + i8 + 4);
        __half2* dp = (__half2*)(d + i8);
        dp[0] = __floats2half2_rn(u.x, u.y);
        dp[1] = __floats2half2_rn(u.z, u.w);
        dp[2] = __floats2half2_rn(v.x, v.y);
        dp[3] = __floats2half2_rn(v.z, v.w);
    }
}

// ---------------------------------------------------------------------------
// LayerNorm: fp32 in, fp16 out
// ---------------------------------------------------------------------------
__global__ void ln_kernel(const float* __restrict__ in, __half* __restrict__ out,
                          const float* __restrict__ gam, const float* __restrict__ bet) {
    int row = blockIdx.x;
    int tid = threadIdx.x;
    const float* x = in + (size_t)row * DD;
    float4 v = *(const float4*)(x + tid * 4);
    float s = v.x + v.y + v.z + v.w;
    float ss = v.x * v.x + v.y * v.y + v.z * v.z + v.w * v.w;
    __shared__ float red[16];
#pragma unroll
    for (int o = 16; o; o >>= 1) {
        s += __shfl_xor_sync(0xffffffffu, s, o);
        ss += __shfl_xor_sync(0xffffffffu, ss, o);
    }
    if ((tid & 31) == 0) { red[(tid >> 5) * 2] = s; red[(tid >> 5) * 2 + 1] = ss; }
    __syncthreads();
    float mu = 0.f, m2 = 0.f;
#pragma unroll
    for (int w = 0; w < 8; w++) { mu += red[2 * w]; m2 += red[2 * w + 1]; }
    mu *= (1.0f / DD);
    float var = m2 * (1.0f / DD) - mu * mu;
    float rstd = rsqrtf(var + 1e-6f);
    float4 gg = *(const float4*)(gam + tid * 4);
    float4 bb = *(const float4*)(bet + tid * 4);
    __half2* op = (__half2*)(out + (size_t)row * DD + tid * 4);
    op[0] = __floats2half2_rn((v.x - mu) * rstd * gg.x + bb.x,
                              (v.y - mu) * rstd * gg.y + bb.y);
    op[1] = __floats2half2_rn((v.z - mu) * rstd * gg.z + bb.z,
                              (v.w - mu) * rstd * gg.w + bb.w);
}

// ---------------------------------------------------------------------------
// Launch
// ---------------------------------------------------------------------------
#define SMEM_H128 ((128 + 128) * 128 * 3)   // 98304
#define SMEM_H64  ((128 + 64) * 128 * 3)    // 73728

extern "C" void kernel_launch(void* const* d_in, const int* in_sizes, int n_in,
                              void* d_out, int out_size) {
    const float* src    = (const float*)d_in[0];
    const int*   mask   = (const int*)d_in[1];
    const float* prior  = (const float*)d_in[2];
    const float* ln1_g  = (const float*)d_in[3];
    const float* ln1_b  = (const float*)d_in[4];
    const float* wq     = (const float*)d_in[5];
    const float* wk     = (const float*)d_in[6];
    const float* wv     = (const float*)d_in[7];
    const float* fc_w   = (const float*)d_in[8];
    const float* ln2_g  = (const float*)d_in[9];
    const float* ln2_b  = (const float*)d_in[10];
    const float* w1_w   = (const float*)d_in[11];
    const float* w1_b   = (const float*)d_in[12];
    const float* w2_w   = (const float*)d_in[13];
    const float* w2_b   = (const float*)d_in[14];

    float* yout = (float*)d_out;
    float* attn = yout + Y_ELEMS;

    __half *xb, *qb, *kb, *vtb, *ob, *zb, *hb, *eb;
    float *yb, *invb, *sumb;
    __half *wq16, *wk16, *wv16, *fc16, *w116, *w216;
    cudaGetSymbolAddress((void**)&xb, g_x16);
    cudaGetSymbolAddress((void**)&qb, g_q16);
    cudaGetSymbolAddress((void**)&kb, g_k16);
    cudaGetSymbolAddress((void**)&vtb, g_vt16);
    cudaGetSymbolAddress((void**)&ob, g_o16);
    cudaGetSymbolAddress((void**)&zb, g_z16);
    cudaGetSymbolAddress((void**)&hb, g_h16);
    cudaGetSymbolAddress((void**)&eb, g_e16);
    cudaGetSymbolAddress((void**)&yb, g_y);
    cudaGetSymbolAddress((void**)&invb, g_inv);
    cudaGetSymbolAddress((void**)&sumb, g_sum);
    cudaGetSymbolAddress((void**)&wq16, g_wq16);
    cudaGetSymbolAddress((void**)&wk16, g_wk16);
    cudaGetSymbolAddress((void**)&wv16, g_wv16);
    cudaGetSymbolAddress((void**)&fc16, g_fc16);
    cudaGetSymbolAddress((void**)&w116, g_w116);
    cudaGetSymbolAddress((void**)&w216, g_w216);

    cudaFuncSetAttribute((const void*)h_gemm<128, 2>,
                         cudaFuncAttributeMaxDynamicSharedMemorySize, SMEM_H128);
    cudaFuncSetAttribute((const void*)h_gemm<64, 4>,
                         cudaFuncAttributeMaxDynamicSharedMemorySize, SMEM_H64);

    // 1) weights -> fp16; zero the atomic row-sum buffer
    {
        dim3 g((DFF * DD / 8 + 255) / 256, 6);
        cvt_all<<<g, 256>>>(wq, wk, wv, fc_w, w1_w, w2_w,
                            wq16, wk16, wv16, fc16, w116, w216);
        zero_sums<<<(NROWS_ATT + 255) / 256, 256>>>(sumb);
    }

    // 2) LN1 -> x fp16
    ln_kernel<<<ROWS, 256>>>(src, xb, ln1_g, ln1_b);

    // 3,4) Q, K projections -> fp16
    {
        dim3 g(DD / 128, ROWS / 128, 1);
        h_gemm<128, 2><<<g, 256, SMEM_H128>>>(xb, wq16, qb, nullptr, nullptr,
            nullptr, nullptr, nullptr, nullptr, nullptr, 2,
            DD, DD, DD, DD, 0, 0, 0, 0, 0, 0, 1);
        h_gemm<128, 2><<<g, 256, SMEM_H128>>>(xb, wk16, kb, nullptr, nullptr,
            nullptr, nullptr, nullptr, nullptr, nullptr, 2,
            DD, DD, DD, DD, 0, 0, 0, 0, 0, 0, 1);
    }
    // 5) Vt = wv @ x^T -> fp16  [DD, ROWS]
    {
        dim3 g(ROWS / 128, DD / 128, 1);
        h_gemm<128, 2><<<g, 256, SMEM_H128>>>(wv16, xb, vtb, nullptr, nullptr,
            nullptr, nullptr, nullptr, nullptr, nullptr, 2,
            DD, DD, DD, ROWS, 0, 0, 0, 0, 0, 0, 1);
    }

    // 6) E = exp(prior*mask*scale*(q.k) - 8) -> fp16 + atomic row sums
    {
        dim3 g(LL / 128, LL / 128, BB * HH);
        h_gemm<128, 2><<<g, 256, SMEM_H128>>>(qb, kb, eb, nullptr, nullptr,
            prior, mask, nullptr, sumb, nullptr, 4,
            DK, DD, DD, LL,
            (long long)LL * DD, (long long)DK,
            (long long)LL * DD, (long long)DK,
            (long long)HH * LL * LL, (long long)LL * LL,
            HH);
    }

    // 7) inv = 1 / sum
    inv_sums<<<(NROWS_ATT + 255) / 256, 256>>>(sumb, invb);

    // 8) O = (E @ Vt^T) * inv -> fp16; stream attn = E * inv -> fp32
    {
        dim3 g(1, LL / 128, BB * HH);
        h_gemm<64, 4><<<g, 256, SMEM_H64>>>(eb, vtb, ob, nullptr, nullptr,
            nullptr, nullptr, invb, nullptr, attn, 2 | 8 | 16,
            LL, LL, ROWS, DD,
            (long long)HH * LL * LL, (long long)LL * LL,
            (long long)LL, (long long)DV * ROWS,
            (long long)LL * DD, (long long)DV,
            HH);
    }

    // 9) y = O @ fc^T + src -> fp32
    {
        dim3 g(DD / 128, ROWS / 128, 1);
        h_gemm<128, 2><<<g, 256, SMEM_H128>>>(ob, fc16, yb, nullptr, src,
            nullptr, nullptr, nullptr, nullptr, nullptr, 0,
            DD, DD, DD, DD, 0, 0, 0, 0, 0, 0, 1);
    }

    // 10) LN2 -> z fp16
    ln_kernel<<<ROWS, 256>>>(yb, zb, ln2_g, ln2_b);

    // 11) h = relu(z @ w1^T + b1) -> fp16
    {
        dim3 g(DFF / 128, ROWS / 128, 1);
        h_gemm<128, 2><<<g, 256, SMEM_H128>>>(zb, w116, hb, w1_b, nullptr,
            nullptr, nullptr, nullptr, nullptr, nullptr, 1 | 2,
            DD, DD, DD, DFF, 0, 0, 0, 0, 0, 0, 1);
    }

    // 12) y_out = h @ w2^T + b2 + y -> fp32 d_out
    {
        dim3 g(DD / 128, ROWS / 128, 1);
        h_gemm<128, 2><<<g, 256, SMEM_H128>>>(hb, w216, yout, w2_b, yb,
            nullptr, nullptr, nullptr, nullptr, nullptr, 0,
            DFF, DFF, DFF, DD, 0, 0, 0, 0, 0, 0, 1);
    }
}